// round 16
// baseline (speedup 1.0000x reference)
#include <cuda_runtime.h>
#include <cuda_fp16.h>
#include <cstdint>

// ---------------- problem constants ----------------
#define TOKENS 512
#define IN_F   4096
#define OUT_F  8192
#define WWORDS (IN_F / 4)            // 1024 int32 words per out-row (4 codes in bits 0..7)

#define M_TILE 128
#define N_TILE 128
#define K_CHUNK 64                   // k elems per pipeline stage (128B rows)
#define NKT    (IN_F / K_CHUNK)      // 64 chunks
#define NSTAGE 3

// stage layout: A fp16 16KB | W fp16 16KB
#define ST_A 0
#define ST_B 16384
#define STAGE_BYTES 32768
#define SMEM_TOTAL (NSTAGE * STAGE_BYTES)   // 98304

// scratch device globals (allowed; no runtime allocation)
__device__ __half g_xh[TOKENS * IN_F];       // 4 MB
__device__ __half g_wd[OUT_F * (size_t)IN_F]; // 64 MB decoded ternary fp16

// ---------------- helpers ----------------
__device__ __forceinline__ uint32_t smem_u32(const void* p) {
    uint32_t a;
    asm("{ .reg .u64 t; cvta.to.shared.u64 t, %1; cvt.u32.u64 %0, t; }" : "=r"(a) : "l"(p));
    return a;
}

#define CP_ASYNC16(dst_u32, src_ptr) \
    asm volatile("cp.async.cg.shared.global [%0], [%1], 16;" :: "r"(dst_u32), "l"(src_ptr) : "memory")
#define CP_COMMIT() asm volatile("cp.async.commit_group;" ::: "memory")
#define CP_WAIT2()  asm volatile("cp.async.wait_group 2;" ::: "memory")

#define LDSM_X4(r, addr) \
    asm volatile("ldmatrix.sync.aligned.m8n8.x4.shared.b16 {%0,%1,%2,%3}, [%4];" \
        : "=r"((r)[0]), "=r"((r)[1]), "=r"((r)[2]), "=r"((r)[3]) : "r"(addr))

#define MMA_F16(c, a, b0, b1) \
    asm volatile("mma.sync.aligned.m16n8k16.row.col.f32.f16.f16.f32 " \
        "{%0,%1,%2,%3}, {%4,%5,%6,%7}, {%8,%9}, {%0,%1,%2,%3};" \
        : "+f"((c)[0]), "+f"((c)[1]), "+f"((c)[2]), "+f"((c)[3]) \
        : "r"((a)[0]), "r"((a)[1]), "r"((a)[2]), "r"((a)[3]), "r"(b0), "r"(b1))

// ---------------- pre-kernel 1: x fp32 -> fp16 ----------------
__global__ void __launch_bounds__(256)
cvt_x_kernel(const float* __restrict__ x) {
    const int i = blockIdx.x * 256 + threadIdx.x;       // float4 index, 524288 total
    const float4 v = reinterpret_cast<const float4*>(x)[i];
    uint2 p;
    __half2 h01 = __floats2half2_rn(v.x, v.y);
    __half2 h23 = __floats2half2_rn(v.z, v.w);
    p.x = *reinterpret_cast<uint32_t*>(&h01);
    p.y = *reinterpret_cast<uint32_t*>(&h23);
    reinterpret_cast<uint2*>(g_xh)[i] = p;
}

// ---------------- pre-kernel 2: decode packed int2 -> fp16 {-1,0,+1} ----------------
// code 0 -> -1 (0xBC00), code 2 -> +1 (0x3C00), codes 1/3 -> 0
__device__ __forceinline__ uint32_t tern2_h(uint32_t w) {
    uint32_t c0 = w & 3u;
    uint32_t c1 = (w >> 2) & 3u;
    uint32_t v0 = (c0 & 1u) ? 0u : ((c0 & 2u) ? 0x3C00u : 0xBC00u);
    uint32_t v1 = (c1 & 1u) ? 0u : ((c1 & 2u) ? 0x3C00u : 0xBC00u);
    return v0 | (v1 << 16);
}

__global__ void __launch_bounds__(256)
decode_w_kernel(const int* __restrict__ wq) {
    const int i = blockIdx.x * 256 + threadIdx.x;       // int2 index, 4M total
    const int2 w = reinterpret_cast<const int2*>(wq)[i];
    uint4 o;
    o.x = tern2_h((uint32_t)w.x);
    o.y = tern2_h((uint32_t)w.x >> 4);
    o.z = tern2_h((uint32_t)w.y);
    o.w = tern2_h((uint32_t)w.y >> 4);
    reinterpret_cast<uint4*>(g_wd)[i] = o;              // 8 fp16 per thread
}

// ---------------- stage loader ----------------
__device__ __forceinline__ void load_stage(uint32_t stg, int kt, int m0, int o0, int tid) {
    // 1024 granules of 16B each per operand (128 rows x 128B), SW128 swizzle
#pragma unroll
    for (int i = 0; i < 4; i++) {
        const int g = tid + i * 256;            // 0..1023
        const int r = g >> 3;                   // row 0..127
        const int q = g & 7;                    // 16B chunk 0..7
        const uint32_t off = (uint32_t)(r * 128 + q * 16);
        const uint32_t sw = off ^ ((off >> 3) & 0x70);
        CP_ASYNC16(stg + ST_A + sw, g_xh + (size_t)(m0 + r) * IN_F + kt * K_CHUNK + q * 8);
        CP_ASYNC16(stg + ST_B + sw, g_wd + (size_t)(o0 + r) * IN_F + kt * K_CHUNK + q * 8);
    }
}

// ---------------- main GEMM kernel ----------------
__global__ void __launch_bounds__(256, 2)
PyTorchTernaryKernel_43112881717530_kernel(const float* __restrict__ alpha,
                                           const float* __restrict__ bias,
                                           float* __restrict__ out) {
    extern __shared__ char smem[];
    const uint32_t sb = smem_u32(smem);
    const int tid = threadIdx.x;
    const int lane = tid & 31;
    const int wid = tid >> 5;
    const int warp_m = wid & 1;     // 2 warps over M (64 rows each)
    const int warp_n = wid >> 1;    // 4 warps over N (32 cols each)
    const int m0 = blockIdx.y * M_TILE;
    const int o0 = blockIdx.x * N_TILE;

    float acc[4][4][4];
#pragma unroll
    for (int a = 0; a < 4; a++)
#pragma unroll
        for (int b = 0; b < 4; b++)
#pragma unroll
            for (int c = 0; c < 4; c++) acc[a][b][c] = 0.0f;

    // A ldmatrix address components: lane -> row (warp_m*64 + lane&15), 16B half (lane>>4)
    const uint32_t abase = (uint32_t)((warp_m * 64 + (lane & 15)) * 128 + (lane >> 4) * 16);
    // B ldmatrix (x4 = 2 n8-tiles x 2 k8-halves): lane -> n row + 16B half
    const uint32_t bbase = (uint32_t)((warp_n * 32 + ((lane >> 4) & 1) * 8 + (lane & 7)) * 128
                                      + ((lane >> 3) & 1) * 16);
    const uint32_t lswz = (uint32_t)((lane & 7) << 4);   // swizzle XOR (row&7)<<4

    // prologue: preload stages 0..2
#pragma unroll
    for (int s = 0; s < NSTAGE; s++) {
        load_stage(sb + s * STAGE_BYTES, s, m0, o0, tid);
        CP_COMMIT();
    }

    int slot = 0;
    for (int kt = 0; kt < NKT; kt++) {
        CP_WAIT2();
        __syncthreads();
        const uint32_t stg = sb + (uint32_t)slot * STAGE_BYTES;

#pragma unroll
        for (int ks = 0; ks < 4; ks++) {
            // ---- B fragments: 2x ldmatrix.x4 covers 4 n8-tiles ----
            uint32_t bf[4][2];
#pragma unroll
            for (int p = 0; p < 2; p++) {
                uint32_t r[4];
                const uint32_t off = bbase + (uint32_t)(p * 2048 + ks * 32);
                LDSM_X4(r, stg + ST_B + (off ^ lswz));
                bf[p * 2 + 0][0] = r[0]; bf[p * 2 + 0][1] = r[1];
                bf[p * 2 + 1][0] = r[2]; bf[p * 2 + 1][1] = r[3];
            }
            // ---- A fragments + MMA ----
#pragma unroll
            for (int mt = 0; mt < 4; mt++) {
                uint32_t af[4];
                const uint32_t off = abase + (uint32_t)(mt * 2048 + ks * 32);
                LDSM_X4(af, stg + ST_A + (off ^ lswz));
#pragma unroll
                for (int nt = 0; nt < 4; nt++)
                    MMA_F16(acc[mt][nt], af, bf[nt][0], bf[nt][1]);
            }
        }

        __syncthreads();
        if (kt + NSTAGE < NKT)
            load_stage(sb + (uint32_t)slot * STAGE_BYTES, kt + NSTAGE, m0, o0, tid);
        CP_COMMIT();   // uniform group accounting
        slot = (slot + 1 == NSTAGE) ? 0 : slot + 1;
    }

    // ---- epilogue: fused alpha/bias, direct fp32 stores ----
    const int rbase = m0 + warp_m * 64 + (lane >> 2);
    const int cbase = o0 + warp_n * 32 + (lane & 3) * 2;
#pragma unroll
    for (int nt = 0; nt < 4; nt++) {
        const int c = cbase + nt * 8;
        const float a0 = alpha[c], a1 = alpha[c + 1];
        const float b0 = bias[c],  b1 = bias[c + 1];
#pragma unroll
        for (int mt = 0; mt < 4; mt++) {
            const int r = rbase + mt * 16;
            float2 v0, v1;
            v0.x = fmaf(acc[mt][nt][0], a0, b0);
            v0.y = fmaf(acc[mt][nt][1], a1, b1);
            v1.x = fmaf(acc[mt][nt][2], a0, b0);
            v1.y = fmaf(acc[mt][nt][3], a1, b1);
            *reinterpret_cast<float2*>(out + (size_t)r * OUT_F + c) = v0;
            *reinterpret_cast<float2*>(out + (size_t)(r + 8) * OUT_F + c) = v1;
        }
    }
}

// ---------------- launch ----------------
extern "C" void kernel_launch(void* const* d_in, const int* in_sizes, int n_in,
                              void* d_out, int out_size) {
    const float* x     = (const float*)d_in[0];
    const int*   wq    = (const int*)d_in[1];
    const float* alpha = (const float*)d_in[2];
    const float* bias  = (const float*)d_in[3];
    float* out = (float*)d_out;

    // 1) x -> fp16 (~2us) and W decode -> fp16 (~20us, DRAM-bound)
    cvt_x_kernel<<<(TOKENS * IN_F / 4) / 256, 256>>>(x);
    decode_w_kernel<<<(OUT_F * WWORDS / 2) / 256, 256>>>(wq);

    // 2) ternary GEMM: grid (64 n-tiles, 4 m-tiles) = 256 CTAs, occ 2 -> one wave
    cudaFuncSetAttribute(PyTorchTernaryKernel_43112881717530_kernel,
                         cudaFuncAttributeMaxDynamicSharedMemorySize, SMEM_TOTAL);
    dim3 grid(OUT_F / N_TILE, TOKENS / M_TILE);
    PyTorchTernaryKernel_43112881717530_kernel<<<grid, 256, SMEM_TOTAL>>>(alpha, bias, out);
}

// round 17
// speedup vs baseline: 1.0742x; 1.0742x over previous
#include <cuda_runtime.h>
#include <cuda_fp16.h>
#include <cstdint>

// ---------------- problem constants ----------------
#define TOKENS 512
#define IN_F   4096
#define OUT_F  8192
#define WWORDS (IN_F / 4)            // 1024 int32 words per out-row (4 codes in bits 0..7)

#define M_TILE 128
#define N_TILE 256
#define K_CHUNK 64                   // k elems per pipeline stage (128B rows)
#define NKT    (IN_F / K_CHUNK)      // 64 chunks
#define NSTAGE 3

// stage layout: A fp16 16KB | W fp16 32KB
#define ST_A 0
#define ST_B 16384
#define STAGE_BYTES 49152
#define SMEM_TOTAL (NSTAGE * STAGE_BYTES)   // 147456

// scratch device global (allowed; no runtime allocation)
__device__ __half g_xh[TOKENS * IN_F];       // 4 MB

// ---------------- helpers ----------------
__device__ __forceinline__ uint32_t smem_u32(const void* p) {
    uint32_t a;
    asm("{ .reg .u64 t; cvta.to.shared.u64 t, %1; cvt.u32.u64 %0, t; }" : "=r"(a) : "l"(p));
    return a;
}

#define CP_ASYNC16(dst_u32, src_ptr) \
    asm volatile("cp.async.cg.shared.global [%0], [%1], 16;" :: "r"(dst_u32), "l"(src_ptr) : "memory")
#define CP_COMMIT() asm volatile("cp.async.commit_group;" ::: "memory")
#define CP_WAIT2()  asm volatile("cp.async.wait_group 2;" ::: "memory")

#define LDSM_X4(r, addr) \
    asm volatile("ldmatrix.sync.aligned.m8n8.x4.shared.b16 {%0,%1,%2,%3}, [%4];" \
        : "=r"((r)[0]), "=r"((r)[1]), "=r"((r)[2]), "=r"((r)[3]) : "r"(addr))

#define MMA_F16(c, a, b0, b1) \
    asm volatile("mma.sync.aligned.m16n8k16.row.col.f32.f16.f16.f32 " \
        "{%0,%1,%2,%3}, {%4,%5,%6,%7}, {%8,%9}, {%0,%1,%2,%3};" \
        : "+f"((c)[0]), "+f"((c)[1]), "+f"((c)[2]), "+f"((c)[3]) \
        : "r"((a)[0]), "r"((a)[1]), "r"((a)[2]), "r"((a)[3]), "r"(b0), "r"(b1))

#define STS128(addr, r0, r1, r2, r3) \
    asm volatile("st.shared.v4.b32 [%0], {%1,%2,%3,%4};" \
        :: "r"(addr), "r"(r0), "r"(r1), "r"(r2), "r"(r3) : "memory")

// PRMT-LUT decode: one packed word (4 codes in bits 7:0) -> 4 fp16 {-1,0,+1} (2 regs).
// table bytes: code0->0xBC (-1 hi-byte), code1->0x00, code2->0x3C (+1), code3->0x00
__device__ __forceinline__ void dec_word(uint32_t w, uint32_t& lo, uint32_t& hi) {
    uint32_t sel = (w & 3u) | ((w << 2) & 0x30u) | ((w << 4) & 0x300u) | ((w << 6) & 0x3000u);
    uint32_t b4 = __byte_perm(0x003C00BCu, 0u, sel);   // byte i = table[code_i]
    lo = __byte_perm(b4, 0u, 0x1404u);                 // {0,B0,0,B1} -> fp16 c0,c1
    hi = __byte_perm(b4, 0u, 0x3424u);                 // {0,B2,0,B3} -> fp16 c2,c3
}

// ---------------- pre-kernel: x fp32 -> fp16 ----------------
__global__ void __launch_bounds__(256)
cvt_x_kernel(const float* __restrict__ x) {
    const int i = blockIdx.x * 256 + threadIdx.x;       // float4 index
    const float4 v = reinterpret_cast<const float4*>(x)[i];
    uint2 p;
    __half2 h01 = __floats2half2_rn(v.x, v.y);
    __half2 h23 = __floats2half2_rn(v.z, v.w);
    p.x = *reinterpret_cast<uint32_t*>(&h01);
    p.y = *reinterpret_cast<uint32_t*>(&h23);
    reinterpret_cast<uint2*>(g_xh)[i] = p;
}

// ---------------- producers ----------------
// A: cp.async 16KB (128 rows x 128B), SW128 swizzle
__device__ __forceinline__ void load_A(uint32_t stg, int kt, int m0, int tid) {
#pragma unroll
    for (int i = 0; i < 4; i++) {
        const int g = tid + i * 256;            // 0..1023
        const int r = g >> 3;                   // row 0..127
        const int q = g & 7;                    // 16B chunk 0..7
        const uint32_t off = (uint32_t)(r * 128 + q * 16);
        const uint32_t sw = off ^ ((off >> 3) & 0x70);
        CP_ASYNC16(stg + ST_A + sw, g_xh + (size_t)(m0 + r) * IN_F + kt * K_CHUNK + q * 8);
    }
}

// B packed LDG: 4 x int4 per thread (covers 256 rows x 16 words)
__device__ __forceinline__ void ldg_B(int4* wr, int kt, int o0,
                                      const int* __restrict__ wq, int tid) {
#pragma unroll
    for (int i = 0; i < 4; i++) {
        const int gp = tid + i * 256;           // 0..1023 (32B group)
        const int r  = gp >> 2;                 // row 0..255
        const int pq = gp & 3;                  // int4 within row slice
        wr[i] = *(const int4*)(wq + (size_t)(o0 + r) * WWORDS + kt * 16 + pq * 4);
    }
}

// B decode + STS: each int4 (4 words = 16 codes) -> 2 x STS.128
__device__ __forceinline__ void sts_B(uint32_t stg, const int4* wr, int tid) {
#pragma unroll
    for (int i = 0; i < 4; i++) {
        const int gp = tid + i * 256;
        const int r  = gp >> 2;
        const int pq = gp & 3;
        uint32_t l0, h0, l1, h1;
        const uint32_t o0b = (uint32_t)(r * 128 + pq * 32);
        dec_word((uint32_t)wr[i].x, l0, h0);
        dec_word((uint32_t)wr[i].y, l1, h1);
        STS128(stg + ST_B + (o0b ^ ((o0b >> 3) & 0x70)), l0, h0, l1, h1);
        dec_word((uint32_t)wr[i].z, l0, h0);
        dec_word((uint32_t)wr[i].w, l1, h1);
        const uint32_t o1b = o0b + 16;
        STS128(stg + ST_B + (o1b ^ ((o1b >> 3) & 0x70)), l0, h0, l1, h1);
    }
}

// ---------------- main GEMM kernel ----------------
__global__ void __launch_bounds__(256, 1)
PyTorchTernaryKernel_43112881717530_kernel(const int* __restrict__ wq,
                                           const float* __restrict__ alpha,
                                           const float* __restrict__ bias,
                                           float* __restrict__ out) {
    extern __shared__ char smem[];
    const uint32_t sb = smem_u32(smem);
    const int tid = threadIdx.x;
    const int lane = tid & 31;
    const int wid = tid >> 5;
    const int warp_m = wid & 1;     // 2 warps over M (64 rows each)
    const int warp_n = wid >> 1;    // 4 warps over N (64 cols each)
    const int m0 = blockIdx.y * M_TILE;
    const int o0 = blockIdx.x * N_TILE;

    float acc[4][8][4];
#pragma unroll
    for (int a = 0; a < 4; a++)
#pragma unroll
        for (int b = 0; b < 8; b++)
#pragma unroll
            for (int c = 0; c < 4; c++) acc[a][b][c] = 0.0f;

    // ldmatrix address components
    const uint32_t abase = (uint32_t)((warp_m * 64 + (lane & 15)) * 128 + (lane >> 4) * 16);
    const uint32_t bbase = (uint32_t)((warp_n * 64 + ((lane >> 4) & 1) * 8 + (lane & 7)) * 128
                                      + ((lane >> 3) & 1) * 16);
    const uint32_t lswz = (uint32_t)((lane & 7) << 4);

    // prologue: stages 0..2 (B decode is synchronous; A via cp.async)
#pragma unroll
    for (int s = 0; s < NSTAGE; s++) {
        int4 wr[4];
        ldg_B(wr, s, o0, wq, tid);
        sts_B(sb + s * STAGE_BYTES, wr, tid);
        load_A(sb + s * STAGE_BYTES, s, m0, tid);
        CP_COMMIT();
    }

    int slot = 0;
    for (int kt = 0; kt < NKT; kt++) {
        CP_WAIT2();
        __syncthreads();
        const uint32_t stg = sb + (uint32_t)slot * STAGE_BYTES;
        const bool pf = (kt + NSTAGE < NKT);

        // prefetch next B packed into registers (latency hides under MMA)
        int4 wr[4];
        if (pf) ldg_B(wr, kt + NSTAGE, o0, wq, tid);

#pragma unroll
        for (int ks = 0; ks < 4; ks++) {
            // B fragments: 4x ldmatrix.x4 -> 8 n8-tiles
            uint32_t bf[8][2];
#pragma unroll
            for (int p = 0; p < 2; p++) {
                uint32_t r[4];
                uint32_t off = bbase + (uint32_t)(p * 4096 + ks * 32);
                LDSM_X4(r, stg + ST_B + (off ^ lswz));
                bf[p * 4 + 0][0] = r[0]; bf[p * 4 + 0][1] = r[1];
                bf[p * 4 + 1][0] = r[2]; bf[p * 4 + 1][1] = r[3];
                off += 2048;   // +16 n rows
                LDSM_X4(r, stg + ST_B + (off ^ lswz));
                bf[p * 4 + 2][0] = r[0]; bf[p * 4 + 2][1] = r[1];
                bf[p * 4 + 3][0] = r[2]; bf[p * 4 + 3][1] = r[3];
            }
            // A fragments + MMA
#pragma unroll
            for (int mt = 0; mt < 4; mt++) {
                uint32_t af[4];
                const uint32_t off = abase + (uint32_t)(mt * 2048 + ks * 32);
                LDSM_X4(af, stg + ST_A + (off ^ lswz));
#pragma unroll
                for (int nt = 0; nt < 8; nt++)
                    MMA_F16(acc[mt][nt], af, bf[nt][0], bf[nt][1]);
            }
        }

        __syncthreads();
        if (pf) {
            sts_B(sb + (uint32_t)slot * STAGE_BYTES, wr, tid);
            load_A(sb + (uint32_t)slot * STAGE_BYTES, kt + NSTAGE, m0, tid);
        }
        CP_COMMIT();   // uniform group accounting
        slot = (slot + 1 == NSTAGE) ? 0 : slot + 1;
    }

    // ---- epilogue: fused alpha/bias, direct fp32 stores ----
    const int rbase = m0 + warp_m * 64 + (lane >> 2);
    const int cbase = o0 + warp_n * 64 + (lane & 3) * 2;
#pragma unroll
    for (int nt = 0; nt < 8; nt++) {
        const int c = cbase + nt * 8;
        const float a0 = alpha[c], a1 = alpha[c + 1];
        const float b0 = bias[c],  b1 = bias[c + 1];
#pragma unroll
        for (int mt = 0; mt < 4; mt++) {
            const int r = rbase + mt * 16;
            float2 v0, v1;
            v0.x = fmaf(acc[mt][nt][0], a0, b0);
            v0.y = fmaf(acc[mt][nt][1], a1, b1);
            v1.x = fmaf(acc[mt][nt][2], a0, b0);
            v1.y = fmaf(acc[mt][nt][3], a1, b1);
            *reinterpret_cast<float2*>(out + (size_t)r * OUT_F + c) = v0;
            *reinterpret_cast<float2*>(out + (size_t)(r + 8) * OUT_F + c) = v1;
        }
    }
}

// ---------------- launch ----------------
extern "C" void kernel_launch(void* const* d_in, const int* in_sizes, int n_in,
                              void* d_out, int out_size) {
    const float* x     = (const float*)d_in[0];
    const int*   wq    = (const int*)d_in[1];
    const float* alpha = (const float*)d_in[2];
    const float* bias  = (const float*)d_in[3];
    float* out = (float*)d_out;

    // 1) x -> fp16 (~6us)
    cvt_x_kernel<<<(TOKENS * IN_F / 4) / 256, 256>>>(x);

    // 2) ternary GEMM with fused W decode: grid (32 n-tiles, 4 m-tiles) = 128 CTAs, 1/SM
    cudaFuncSetAttribute(PyTorchTernaryKernel_43112881717530_kernel,
                         cudaFuncAttributeMaxDynamicSharedMemorySize, SMEM_TOTAL);
    dim3 grid(OUT_F / N_TILE, TOKENS / M_TILE);
    PyTorchTernaryKernel_43112881717530_kernel<<<grid, 256, SMEM_TOTAL>>>(wq, alpha, bias, out);
}